// round 7
// baseline (speedup 1.0000x reference)
#include <cuda_runtime.h>
#include <cuda_bf16.h>
#include <cstdint>

// HarmonicAwaredAttention via warp-level HMMA (mma.sync, arch-agnostic PTX).
// One block per sequence n = b*512 + t; 256 threads (8 warps).
// GEMMs: m16n8k16 bf16 MMA, fp32 emulated with bf16 hi/lo 3-term split.
// R7: warp grid 4(M)x2(N), warp tile 32x64 -> A-LDSM traffic cut 4x.
// A: smem bf16 hi/lo [128x136]. B: gmem fragment-linear (LDG.64, L2-resident).
// Attention: scalar fp32 sparse-harmonic, K/V/Q fp32 in smem.

#define TT 512
#define NTHREADS 256
#define LDH_B  272            // bf16 row stride in bytes (136 elems)
#define LDF    132            // fp32 row stride in floats

// smem byte offsets
#define HHI_OFF 0
#define HLO_OFF 34816
#define QS_OFF  0              // fp32 Q overlays H region (sequenced by syncs)
#define KS_OFF  69632
#define VS_OFF  137216
#define SMEM_TOTAL 204800

// weights, fragment-linear: [gemm][sel hi/lo][ks 0..7][ntile 0..15][lane 0..31] uint2
__device__ __align__(16) uint2 g_wfrag[16 * 8192];
__device__ float g_pe[128 * 128];     // g_pe[c*128 + f]

__device__ __forceinline__ uint32_t smem_u32(const void* p) {
    uint32_t a;
    asm("{ .reg .u64 t; cvta.to.shared.u64 t, %1; cvt.u32.u64 %0, t; }" : "=r"(a) : "l"(p));
    return a;
}

#define LDSM(r, addr) \
    asm volatile("ldmatrix.sync.aligned.m8n8.x4.shared.b16 {%0,%1,%2,%3}, [%4];" \
        : "=r"((r)[0]), "=r"((r)[1]), "=r"((r)[2]), "=r"((r)[3]) : "r"(addr))

#define MMA(dp, a, b) \
    asm volatile("mma.sync.aligned.m16n8k16.row.col.f32.bf16.bf16.f32 " \
        "{%0,%1,%2,%3},{%4,%5,%6,%7},{%8,%9},{%0,%1,%2,%3};" \
        : "+f"((dp)[0]), "+f"((dp)[1]), "+f"((dp)[2]), "+f"((dp)[3]) \
        : "r"((a)[0]), "r"((a)[1]), "r"((a)[2]), "r"((a)[3]), "r"((b).x), "r"((b).y))

// ---------------- prologue: fragment-pack weights + PE table ----------------
// gemm g = 4*layer + {0:Wk,1:Wv,2:Wq,3:Wo}.  B[n][k] = W[k][n].
// entry e: lane=e&31, j=(e>>5)&15 (n-tile), ks=(e>>9)&7, sel=e>>12 (0 hi, 1 lo).
// lane fragment: n = 8j + (lane>>2); k0 = 16ks + 2(lane&3);
// word0 = pack(B[k0][n], B[k0+1][n]); word1 = pack(B[k0+8][n], B[k0+9][n]).
__global__ void prep_w(const float* __restrict__ Wq, const float* __restrict__ Wk,
                       const float* __restrict__ Wv, const float* __restrict__ Wo)
{
    int g = blockIdx.x;
    if (g == 16) {   // PE table
        for (int idx = threadIdx.x; idx < 128 * 128; idx += blockDim.x) {
            int c = idx >> 7, f = idx & 127;
            float e     = (float)(c & ~1) * (1.0f / 128.0f);
            float denom = exp2f(e * 13.287712379549449f);   // 10000^(i/128)
            float ang   = (float)f / denom;
            g_pe[c * 128 + f] = (c & 1) ? cosf(ang) : sinf(ang);
        }
        return;
    }
    int l = g >> 2, m = g & 3;
    const float* src = (m == 0 ? Wk : m == 1 ? Wv : m == 2 ? Wq : Wo) + l * 16384;
    for (int e = threadIdx.x; e < 8192; e += blockDim.x) {
        int lane = e & 31, j = (e >> 5) & 15, ks = (e >> 9) & 7, sel = (e >> 12) & 1;
        int n  = 8 * j + (lane >> 2);
        int k0 = 16 * ks + 2 * (lane & 3);
        float w00 = src[k0 * 128 + n],       w01 = src[(k0 + 1) * 128 + n];
        float w10 = src[(k0 + 8) * 128 + n], w11 = src[(k0 + 9) * 128 + n];
        __nv_bfloat162 p0, p1;
        if (sel == 0) {
            p0 = __floats2bfloat162_rn(w00, w01);
            p1 = __floats2bfloat162_rn(w10, w11);
        } else {
            float h00 = __bfloat162float(__float2bfloat16(w00));
            float h01 = __bfloat162float(__float2bfloat16(w01));
            float h10 = __bfloat162float(__float2bfloat16(w10));
            float h11 = __bfloat162float(__float2bfloat16(w11));
            p0 = __floats2bfloat162_rn(w00 - h00, w01 - h01);
            p1 = __floats2bfloat162_rn(w10 - h10, w11 - h11);
        }
        uint2 o;
        o.x = *(uint32_t*)&p0;
        o.y = *(uint32_t*)&p1;
        g_wfrag[g * 8192 + e] = o;
    }
}

// ------------- GEMM: warp (mw,nw) computes D[32 rows x 64 cols] -------------
// d[mt*8 + jj][4]: mt in 0..1 (16-row tiles), jj in 0..7 (8-col tiles).
__device__ __forceinline__ void gemm_mma(uint32_t a_hi_lane, uint32_t a_lo_lane,
                                         const uint2* __restrict__ wf,
                                         int mw, int nw, float (*d)[4])
{
#pragma unroll
    for (int i = 0; i < 16; i++) { d[i][0] = 0.f; d[i][1] = 0.f; d[i][2] = 0.f; d[i][3] = 0.f; }

    // B fragment base for this warp's N half: entries (sel, ks, j=8*nw+jj, lane)
    const uint2* wfb = wf + (8 * nw) * 32;     // + lane added by caller offset in wf

    uint2 bh[8], bl[8];
#pragma unroll
    for (int jj = 0; jj < 8; jj++) {
        bh[jj] = __ldg(wfb + jj * 32);
        bl[jj] = __ldg(wfb + 4096 + jj * 32);
    }

    const uint32_t a_row_off = (uint32_t)(mw * 32) * LDH_B;

#pragma unroll
    for (int ks = 0; ks < 8; ks++) {
        uint32_t ah[2][4], al[2][4];
#pragma unroll
        for (int mt = 0; mt < 2; mt++) {
            uint32_t off = a_row_off + (uint32_t)(mt * 16) * LDH_B + (uint32_t)ks * 32;
            LDSM(ah[mt], a_hi_lane + off);
            LDSM(al[mt], a_lo_lane + off);
        }
        uint2 nbh[8], nbl[8];
        if (ks < 7) {
            const uint2* p = wfb + (ks + 1) * 512;
#pragma unroll
            for (int jj = 0; jj < 8; jj++) {
                nbh[jj] = __ldg(p + jj * 32);
                nbl[jj] = __ldg(p + 4096 + jj * 32);
            }
        }
#pragma unroll
        for (int mt = 0; mt < 2; mt++) {
#pragma unroll
            for (int jj = 0; jj < 8; jj++) {
                MMA(d[mt * 8 + jj], ah[mt], bh[jj]);
                MMA(d[mt * 8 + jj], ah[mt], bl[jj]);
                MMA(d[mt * 8 + jj], al[mt], bh[jj]);
            }
        }
#pragma unroll
        for (int jj = 0; jj < 8; jj++) { bh[jj] = nbh[jj]; bl[jj] = nbl[jj]; }
    }
}

// D + bias -> fp32 smem buffer [128][132]
__device__ __forceinline__ void epi_f32(float (*d)[4], float* buf, const float* bias,
                                        int mw, int nw, int lane)
{
    int rq = lane >> 2, cq = 2 * (lane & 3);
#pragma unroll
    for (int jj = 0; jj < 8; jj++) {
        int c = 64 * nw + 8 * jj + cq;
        float b0 = __ldg(&bias[c]), b1 = __ldg(&bias[c + 1]);
#pragma unroll
        for (int mt = 0; mt < 2; mt++) {
            int r0 = 32 * mw + 16 * mt + rq;
            float2 v0 = make_float2(d[mt*8+jj][0] + b0, d[mt*8+jj][1] + b1);
            float2 v1 = make_float2(d[mt*8+jj][2] + b0, d[mt*8+jj][3] + b1);
            *(float2*)&buf[r0 * LDF + c]       = v0;
            *(float2*)&buf[(r0 + 8) * LDF + c] = v1;
        }
    }
}

// D + bias -> bf16 hi/lo H buffers
__device__ __forceinline__ void epi_bf16(float (*d)[4], unsigned char* sm,
                                         const float* bias, int mw, int nw, int lane)
{
    int rq = lane >> 2, cq = 2 * (lane & 3);
#pragma unroll
    for (int jj = 0; jj < 8; jj++) {
        int c = 64 * nw + 8 * jj + cq;
        float b0 = __ldg(&bias[c]), b1 = __ldg(&bias[c + 1]);
#pragma unroll
        for (int mt = 0; mt < 2; mt++) {
            int r0 = 32 * mw + 16 * mt + rq;
#pragma unroll
            for (int hh = 0; hh < 2; hh++) {
                int r = r0 + 8 * hh;
                float v0 = d[mt*8+jj][2*hh]     + b0;
                float v1 = d[mt*8+jj][2*hh + 1] + b1;
                __nv_bfloat162 hi2 = __floats2bfloat162_rn(v0, v1);
                float2 hf = __bfloat1622float2(hi2);
                __nv_bfloat162 lo2 = __floats2bfloat162_rn(v0 - hf.x, v1 - hf.y);
                *(uint32_t*)(sm + HHI_OFF + r * LDH_B + c * 2) = *(uint32_t*)&hi2;
                *(uint32_t*)(sm + HLO_OFF + r * LDH_B + c * 2) = *(uint32_t*)&lo2;
            }
        }
    }
}

// D + bias -> gmem out (transposed: out[c][r], channel stride 65536)
__device__ __forceinline__ void epi_out(float (*d)[4], float* ob, const float* bias,
                                        int mw, int nw, int lane)
{
    int rq = lane >> 2, cq = 2 * (lane & 3);
#pragma unroll
    for (int jj = 0; jj < 8; jj++) {
        int c = 64 * nw + 8 * jj + cq;
        float b0 = __ldg(&bias[c]), b1 = __ldg(&bias[c + 1]);
#pragma unroll
        for (int mt = 0; mt < 2; mt++) {
            int r0 = 32 * mw + 16 * mt + rq;
            ob[(size_t)c * 65536 + r0]           = d[mt*8+jj][0] + b0;
            ob[(size_t)(c + 1) * 65536 + r0]     = d[mt*8+jj][1] + b1;
            ob[(size_t)c * 65536 + r0 + 8]       = d[mt*8+jj][2] + b0;
            ob[(size_t)(c + 1) * 65536 + r0 + 8] = d[mt*8+jj][3] + b1;
        }
    }
}

// 64 fp32 vals (one row, one head-half) -> bf16 hi/lo into H buffers
__device__ __forceinline__ void stage_rowvals(const float* v, unsigned char* sm,
                                              int row, int c0)
{
#pragma unroll
    for (int i = 0; i < 32; i++) {
        float a = v[2 * i], b = v[2 * i + 1];
        __nv_bfloat162 hi2 = __floats2bfloat162_rn(a, b);
        float2 hf = __bfloat1622float2(hi2);
        __nv_bfloat162 lo2 = __floats2bfloat162_rn(a - hf.x, b - hf.y);
        *(uint32_t*)(sm + HHI_OFF + row * LDH_B + (c0 + 2 * i) * 2) = *(uint32_t*)&hi2;
        *(uint32_t*)(sm + HLO_OFF + row * LDH_B + (c0 + 2 * i) * 2) = *(uint32_t*)&lo2;
    }
}

extern __shared__ unsigned char smem[];

__global__ void __launch_bounds__(NTHREADS, 1)
hattn_mma(const float* __restrict__ x,
          const float* __restrict__ bq, const float* __restrict__ bk,
          const float* __restrict__ bv, const float* __restrict__ bo,
          float* __restrict__ out)
{
    const int tid = threadIdx.x;
    const int w = tid >> 5, lane = tid & 31;
    const int mw = w & 3, nw = w >> 2;          // warp grid 4(M) x 2(N)
    const int bi = blockIdx.x / TT;
    const int t  = blockIdx.x % TT;

    float* Qs = (float*)(smem + QS_OFF);
    float* Ks = (float*)(smem + KS_OFF);
    float* Vs = (float*)(smem + VS_OFF);

    const uint32_t smbase = smem_u32(smem);
    const uint32_t a_hi_lane = smbase + HHI_OFF + (lane & 15) * LDH_B + (lane >> 4) * 16;
    const uint32_t a_lo_lane = smbase + HLO_OFF + (lane & 15) * LDH_B + (lane >> 4) * 16;

    // attention / staging thread mapping
    const int row = tid >> 1;
    const int c0  = (tid & 1) * 64;

    // ---- stage H = x + PE ----
    {
        const float* xb = x + (size_t)bi * 8388608 + (size_t)t * 128;
        float v[64];
#pragma unroll
        for (int c = 0; c < 64; c++)
            v[c] = xb[(size_t)(c0 + c) * 65536 + row] + g_pe[(c0 + c) * 128 + row];
        stage_rowvals(v, smem, row, c0);
    }

    const int deltas[11] = {-124, -111, -96, -76, -48, 0, 48, 76, 96, 111, 124};
    float d[16][4];

#pragma unroll 1
    for (int l = 0; l < 4; l++) {
        __syncthreads();                                     // H staged/visible

        gemm_mma(a_hi_lane, a_lo_lane, g_wfrag + (4*l + 0) * 8192 + lane, mw, nw, d);
        epi_f32(d, Ks, bk + l * 128, mw, nw, lane);
        gemm_mma(a_hi_lane, a_lo_lane, g_wfrag + (4*l + 1) * 8192 + lane, mw, nw, d);
        epi_f32(d, Vs, bv + l * 128, mw, nw, lane);
        gemm_mma(a_hi_lane, a_lo_lane, g_wfrag + (4*l + 2) * 8192 + lane, mw, nw, d);
        __syncthreads();                                     // all H reads done
        epi_f32(d, Qs, bq + l * 128, mw, nw, lane);          // Q overlays H region
        __syncthreads();                                     // Q/K/V visible

        // ---- sparse harmonic attention: thread owns (row, head=c0/64) ----
        float o[64];
        {
            float q[64];
            const float* qp = &Qs[row * LDF + c0];
#pragma unroll
            for (int i = 0; i < 64; i++) q[i] = qp[i];

            float sv[11];
#pragma unroll
            for (int dd = 0; dd < 11; dd++) {
                int j = row + deltas[dd];
                float s = -1e30f;
                if ((unsigned)j < 128u) {
                    const float* kp = &Ks[j * LDF + c0];
                    float a = 0.f;
#pragma unroll
                    for (int i = 0; i < 16; i++) {
                        float4 kk = *(const float4*)&kp[i * 4];
                        a = fmaf(q[4*i],   kk.x, a);
                        a = fmaf(q[4*i+1], kk.y, a);
                        a = fmaf(q[4*i+2], kk.z, a);
                        a = fmaf(q[4*i+3], kk.w, a);
                    }
                    s = a * 0.125f;
                }
                sv[dd] = s;
            }
            float m = sv[0];
#pragma unroll
            for (int dd = 1; dd < 11; dd++) m = fmaxf(m, sv[dd]);
            float ev[11], sum = 0.f;
#pragma unroll
            for (int dd = 0; dd < 11; dd++) { float e = expf(sv[dd] - m); ev[dd] = e; sum += e; }
            float inv = 1.f / sum;
#pragma unroll
            for (int i = 0; i < 64; i++) o[i] = 0.f;
#pragma unroll
            for (int dd = 0; dd < 11; dd++) {
                int j = row + deltas[dd];
                if ((unsigned)j < 128u) {
                    float wj = ev[dd] * inv;
                    const float* vp = &Vs[j * LDF + c0];
#pragma unroll
                    for (int i = 0; i < 16; i++) {
                        float4 vv = *(const float4*)&vp[i * 4];
                        o[4*i]   = fmaf(wj, vv.x, o[4*i]);
                        o[4*i+1] = fmaf(wj, vv.y, o[4*i+1]);
                        o[4*i+2] = fmaf(wj, vv.z, o[4*i+2]);
                        o[4*i+3] = fmaf(wj, vv.w, o[4*i+3]);
                    }
                }
            }
        }
        __syncthreads();                                     // all Q reads done
        stage_rowvals(o, smem, row, c0);                     // O -> H buffers
        __syncthreads();                                     // O staged

        gemm_mma(a_hi_lane, a_lo_lane, g_wfrag + (4*l + 3) * 8192 + lane, mw, nw, d);
        __syncthreads();                                     // all O reads done
        if (l < 3) {
            epi_bf16(d, smem, bo + l * 128, mw, nw, lane);   // H_new staged
        } else {
            float* ob = out + (size_t)bi * 8388608 + (size_t)t * 128;
            epi_out(d, ob, bo + l * 128, mw, nw, lane);
        }
    }
}

extern "C" void kernel_launch(void* const* d_in, const int* in_sizes, int n_in,
                              void* d_out, int out_size)
{
    const float* x  = (const float*)d_in[0];
    const float* Wq = (const float*)d_in[1];
    const float* bq = (const float*)d_in[2];
    const float* Wk = (const float*)d_in[3];
    const float* bk = (const float*)d_in[4];
    const float* Wv = (const float*)d_in[5];
    const float* bv = (const float*)d_in[6];
    const float* Wo = (const float*)d_in[7];
    const float* bo = (const float*)d_in[8];
    float* out = (float*)d_out;

    const int NB = in_sizes[0] / (128 * TT * 128);   // batch (4)

    prep_w<<<17, 256>>>(Wq, Wk, Wv, Wo);

    cudaFuncSetAttribute(hattn_mma, cudaFuncAttributeMaxDynamicSharedMemorySize, SMEM_TOTAL);
    hattn_mma<<<NB * TT, NTHREADS, SMEM_TOTAL>>>(x, bq, bk, bv, bo, out);
}

// round 8
// speedup vs baseline: 1.0310x; 1.0310x over previous
#include <cuda_runtime.h>
#include <cuda_bf16.h>
#include <cstdint>

// HarmonicAwaredAttention via warp-level HMMA (mma.sync, arch-agnostic PTX).
// One block per sequence n = b*512 + t; 256 threads (8 warps).
// GEMMs: m16n8k16 bf16 MMA, fp32 emulated with bf16 hi/lo 3-term split.
// R8: warp grid 2(M)x4(N), tile 64x32; B hi/lo fused in uint4 LDG.128;
//     wrap-around prefetch; target: no register spills (R7 hit 255 regs).
// Attention: scalar fp32 sparse-harmonic, K/V/Q fp32 in smem.

#define TT 512
#define NTHREADS 256
#define LDH_B  272            // bf16 row stride in bytes (136 elems)
#define LDF    132            // fp32 row stride in floats

// smem byte offsets
#define HHI_OFF 0
#define HLO_OFF 34816
#define QS_OFF  0              // fp32 Q overlays H region (sequenced by syncs)
#define KS_OFF  69632
#define VS_OFF  137216
#define SMEM_TOTAL 204800

// weights, fragment-linear uint4: [gemm][ks 0..7][j 0..15][lane 0..31]
// uint4 = {bh.x, bh.y, bl.x, bl.y}
__device__ __align__(16) uint4 g_wfrag[16 * 4096];
__device__ float g_pe[128 * 128];     // g_pe[c*128 + f]

__device__ __forceinline__ uint32_t smem_u32(const void* p) {
    uint32_t a;
    asm("{ .reg .u64 t; cvta.to.shared.u64 t, %1; cvt.u32.u64 %0, t; }" : "=r"(a) : "l"(p));
    return a;
}

#define LDSM(r, addr) \
    asm volatile("ldmatrix.sync.aligned.m8n8.x4.shared.b16 {%0,%1,%2,%3}, [%4];" \
        : "=r"((r)[0]), "=r"((r)[1]), "=r"((r)[2]), "=r"((r)[3]) : "r"(addr))

#define MMA(dp, a, bx, by) \
    asm volatile("mma.sync.aligned.m16n8k16.row.col.f32.bf16.bf16.f32 " \
        "{%0,%1,%2,%3},{%4,%5,%6,%7},{%8,%9},{%0,%1,%2,%3};" \
        : "+f"((dp)[0]), "+f"((dp)[1]), "+f"((dp)[2]), "+f"((dp)[3]) \
        : "r"((a)[0]), "r"((a)[1]), "r"((a)[2]), "r"((a)[3]), "r"(bx), "r"(by))

// ---------------- prologue: fragment-pack weights + PE table ----------------
// gemm g = 4*layer + {0:Wk,1:Wv,2:Wq,3:Wo}.  B[n][k] = W[k][n].
// entry e: lane=e&31, j=(e>>5)&15 (n-tile), ks=e>>9.
// lane fragment: n = 8j + (lane>>2); k0 = 16ks + 2(lane&3);
// hi word0 = pack(B[k0][n], B[k0+1][n]); hi word1 = pack(B[k0+8][n], B[k0+9][n]);
// lo words = residuals. Stored as one uint4.
__global__ void prep_w(const float* __restrict__ Wq, const float* __restrict__ Wk,
                       const float* __restrict__ Wv, const float* __restrict__ Wo)
{
    int g = blockIdx.x;
    if (g == 16) {   // PE table
        for (int idx = threadIdx.x; idx < 128 * 128; idx += blockDim.x) {
            int c = idx >> 7, f = idx & 127;
            float e     = (float)(c & ~1) * (1.0f / 128.0f);
            float denom = exp2f(e * 13.287712379549449f);   // 10000^(i/128)
            float ang   = (float)f / denom;
            g_pe[c * 128 + f] = (c & 1) ? cosf(ang) : sinf(ang);
        }
        return;
    }
    int l = g >> 2, m = g & 3;
    const float* src = (m == 0 ? Wk : m == 1 ? Wv : m == 2 ? Wq : Wo) + l * 16384;
    for (int e = threadIdx.x; e < 4096; e += blockDim.x) {
        int lane = e & 31, j = (e >> 5) & 15, ks = e >> 9;
        int n  = 8 * j + (lane >> 2);
        int k0 = 16 * ks + 2 * (lane & 3);
        float w00 = src[k0 * 128 + n],       w01 = src[(k0 + 1) * 128 + n];
        float w10 = src[(k0 + 8) * 128 + n], w11 = src[(k0 + 9) * 128 + n];
        __nv_bfloat162 h0 = __floats2bfloat162_rn(w00, w01);
        __nv_bfloat162 h1 = __floats2bfloat162_rn(w10, w11);
        float2 f0 = __bfloat1622float2(h0), f1 = __bfloat1622float2(h1);
        __nv_bfloat162 l0 = __floats2bfloat162_rn(w00 - f0.x, w01 - f0.y);
        __nv_bfloat162 l1 = __floats2bfloat162_rn(w10 - f1.x, w11 - f1.y);
        uint4 o;
        o.x = *(uint32_t*)&h0;  o.y = *(uint32_t*)&h1;
        o.z = *(uint32_t*)&l0;  o.w = *(uint32_t*)&l1;
        g_wfrag[g * 4096 + e] = o;
    }
}

// ------------- GEMM: warp (mw,nw) computes D[64 rows x 32 cols] -------------
// d[mt*4 + jj][4]: mt in 0..3 (16-row tiles), jj in 0..3 (8-col tiles).
// wf is pre-offset: g_wfrag + g*4096 + (4*nw)*32 + lane.
__device__ __forceinline__ void gemm_mma(uint32_t a_hi_lane, uint32_t a_lo_lane,
                                         const uint4* __restrict__ wf,
                                         int mw, float (*d)[4])
{
#pragma unroll
    for (int i = 0; i < 16; i++) { d[i][0] = 0.f; d[i][1] = 0.f; d[i][2] = 0.f; d[i][3] = 0.f; }

    uint4 b[4];
#pragma unroll
    for (int jj = 0; jj < 4; jj++) b[jj] = __ldg(wf + jj * 32);

    const uint32_t a_row_off = (uint32_t)(mw * 64) * LDH_B;

#pragma unroll
    for (int ks = 0; ks < 8; ks++) {
        uint32_t ah[4][4], al[4][4];
#pragma unroll
        for (int mt = 0; mt < 4; mt++) {
            uint32_t off = a_row_off + (uint32_t)(mt * 16) * LDH_B + (uint32_t)ks * 32;
            LDSM(ah[mt], a_hi_lane + off);
            LDSM(al[mt], a_lo_lane + off);
        }
        uint4 nb[4];
        {   // wrap-around prefetch (ks=7 reloads ks=0; harmless, unconditional)
            const uint4* p = wf + (((ks + 1) & 7) * 512);
#pragma unroll
            for (int jj = 0; jj < 4; jj++) nb[jj] = __ldg(p + jj * 32);
        }
#pragma unroll
        for (int mt = 0; mt < 4; mt++) {
#pragma unroll
            for (int jj = 0; jj < 4; jj++) {
                MMA(d[mt * 4 + jj], ah[mt], b[jj].x, b[jj].y);   // Ah*Bh
                MMA(d[mt * 4 + jj], ah[mt], b[jj].z, b[jj].w);   // Ah*Bl
                MMA(d[mt * 4 + jj], al[mt], b[jj].x, b[jj].y);   // Al*Bh
            }
        }
#pragma unroll
        for (int jj = 0; jj < 4; jj++) b[jj] = nb[jj];
    }
}

// D + bias -> fp32 smem buffer [128][132]
__device__ __forceinline__ void epi_f32(float (*d)[4], float* buf, const float* bias,
                                        int mw, int nw, int lane)
{
    int rq = lane >> 2, cq = 2 * (lane & 3);
#pragma unroll
    for (int jj = 0; jj < 4; jj++) {
        int c = 32 * nw + 8 * jj + cq;
        float b0 = __ldg(&bias[c]), b1 = __ldg(&bias[c + 1]);
#pragma unroll
        for (int mt = 0; mt < 4; mt++) {
            int r0 = 64 * mw + 16 * mt + rq;
            float2 v0 = make_float2(d[mt*4+jj][0] + b0, d[mt*4+jj][1] + b1);
            float2 v1 = make_float2(d[mt*4+jj][2] + b0, d[mt*4+jj][3] + b1);
            *(float2*)&buf[r0 * LDF + c]       = v0;
            *(float2*)&buf[(r0 + 8) * LDF + c] = v1;
        }
    }
}

// D + bias -> bf16 hi/lo H buffers
__device__ __forceinline__ void epi_bf16(float (*d)[4], unsigned char* sm,
                                         const float* bias, int mw, int nw, int lane)
{
    int rq = lane >> 2, cq = 2 * (lane & 3);
#pragma unroll
    for (int jj = 0; jj < 4; jj++) {
        int c = 32 * nw + 8 * jj + cq;
        float b0 = __ldg(&bias[c]), b1 = __ldg(&bias[c + 1]);
#pragma unroll
        for (int mt = 0; mt < 4; mt++) {
            int r0 = 64 * mw + 16 * mt + rq;
#pragma unroll
            for (int hh = 0; hh < 2; hh++) {
                int r = r0 + 8 * hh;
                float v0 = d[mt*4+jj][2*hh]     + b0;
                float v1 = d[mt*4+jj][2*hh + 1] + b1;
                __nv_bfloat162 hi2 = __floats2bfloat162_rn(v0, v1);
                float2 hf = __bfloat1622float2(hi2);
                __nv_bfloat162 lo2 = __floats2bfloat162_rn(v0 - hf.x, v1 - hf.y);
                *(uint32_t*)(sm + HHI_OFF + r * LDH_B + c * 2) = *(uint32_t*)&hi2;
                *(uint32_t*)(sm + HLO_OFF + r * LDH_B + c * 2) = *(uint32_t*)&lo2;
            }
        }
    }
}

// D + bias -> gmem out (transposed: out[c][r], channel stride 65536)
__device__ __forceinline__ void epi_out(float (*d)[4], float* ob, const float* bias,
                                        int mw, int nw, int lane)
{
    int rq = lane >> 2, cq = 2 * (lane & 3);
#pragma unroll
    for (int jj = 0; jj < 4; jj++) {
        int c = 32 * nw + 8 * jj + cq;
        float b0 = __ldg(&bias[c]), b1 = __ldg(&bias[c + 1]);
#pragma unroll
        for (int mt = 0; mt < 4; mt++) {
            int r0 = 64 * mw + 16 * mt + rq;
            ob[(size_t)c * 65536 + r0]           = d[mt*4+jj][0] + b0;
            ob[(size_t)(c + 1) * 65536 + r0]     = d[mt*4+jj][1] + b1;
            ob[(size_t)c * 65536 + r0 + 8]       = d[mt*4+jj][2] + b0;
            ob[(size_t)(c + 1) * 65536 + r0 + 8] = d[mt*4+jj][3] + b1;
        }
    }
}

// 64 fp32 vals (one row, one head-half) -> bf16 hi/lo into H buffers
__device__ __forceinline__ void stage_rowvals(const float* v, unsigned char* sm,
                                              int row, int c0)
{
#pragma unroll
    for (int i = 0; i < 32; i++) {
        float a = v[2 * i], b = v[2 * i + 1];
        __nv_bfloat162 hi2 = __floats2bfloat162_rn(a, b);
        float2 hf = __bfloat1622float2(hi2);
        __nv_bfloat162 lo2 = __floats2bfloat162_rn(a - hf.x, b - hf.y);
        *(uint32_t*)(sm + HHI_OFF + row * LDH_B + (c0 + 2 * i) * 2) = *(uint32_t*)&hi2;
        *(uint32_t*)(sm + HLO_OFF + row * LDH_B + (c0 + 2 * i) * 2) = *(uint32_t*)&lo2;
    }
}

extern __shared__ unsigned char smem[];

__global__ void __launch_bounds__(NTHREADS, 1)
hattn_mma(const float* __restrict__ x,
          const float* __restrict__ bq, const float* __restrict__ bk,
          const float* __restrict__ bv, const float* __restrict__ bo,
          float* __restrict__ out)
{
    const int tid = threadIdx.x;
    const int w = tid >> 5, lane = tid & 31;
    const int mw = w & 1, nw = w >> 1;          // warp grid 2(M) x 4(N)
    const int bi = blockIdx.x / TT;
    const int t  = blockIdx.x % TT;

    float* Qs = (float*)(smem + QS_OFF);
    float* Ks = (float*)(smem + KS_OFF);
    float* Vs = (float*)(smem + VS_OFF);

    const uint32_t smbase = smem_u32(smem);
    const uint32_t a_hi_lane = smbase + HHI_OFF + (lane & 15) * LDH_B + (lane >> 4) * 16;
    const uint32_t a_lo_lane = smbase + HLO_OFF + (lane & 15) * LDH_B + (lane >> 4) * 16;

    const int wfoff = (4 * nw) * 32 + lane;     // B fragment base offset for this warp

    // attention / staging thread mapping
    const int row = tid >> 1;
    const int c0  = (tid & 1) * 64;

    // ---- stage H = x + PE ----
    {
        const float* xb = x + (size_t)bi * 8388608 + (size_t)t * 128;
        float v[64];
#pragma unroll
        for (int c = 0; c < 64; c++)
            v[c] = xb[(size_t)(c0 + c) * 65536 + row] + g_pe[(c0 + c) * 128 + row];
        stage_rowvals(v, smem, row, c0);
    }

    const int deltas[11] = {-124, -111, -96, -76, -48, 0, 48, 76, 96, 111, 124};
    float d[16][4];

#pragma unroll 1
    for (int l = 0; l < 4; l++) {
        __syncthreads();                                     // H staged/visible

        gemm_mma(a_hi_lane, a_lo_lane, g_wfrag + (4*l + 0) * 4096 + wfoff, mw, d);
        epi_f32(d, Ks, bk + l * 128, mw, nw, lane);
        gemm_mma(a_hi_lane, a_lo_lane, g_wfrag + (4*l + 1) * 4096 + wfoff, mw, d);
        epi_f32(d, Vs, bv + l * 128, mw, nw, lane);
        gemm_mma(a_hi_lane, a_lo_lane, g_wfrag + (4*l + 2) * 4096 + wfoff, mw, d);
        __syncthreads();                                     // all H reads done
        epi_f32(d, Qs, bq + l * 128, mw, nw, lane);          // Q overlays H region
        __syncthreads();                                     // Q/K/V visible

        // ---- sparse harmonic attention: thread owns (row, head=c0/64) ----
        float o[64];
        {
            float q[64];
            const float* qp = &Qs[row * LDF + c0];
#pragma unroll
            for (int i = 0; i < 64; i++) q[i] = qp[i];

            float sv[11];
#pragma unroll
            for (int dd = 0; dd < 11; dd++) {
                int j = row + deltas[dd];
                float s = -1e30f;
                if ((unsigned)j < 128u) {
                    const float* kp = &Ks[j * LDF + c0];
                    float a = 0.f;
#pragma unroll
                    for (int i = 0; i < 16; i++) {
                        float4 kk = *(const float4*)&kp[i * 4];
                        a = fmaf(q[4*i],   kk.x, a);
                        a = fmaf(q[4*i+1], kk.y, a);
                        a = fmaf(q[4*i+2], kk.z, a);
                        a = fmaf(q[4*i+3], kk.w, a);
                    }
                    s = a * 0.125f;
                }
                sv[dd] = s;
            }
            float m = sv[0];
#pragma unroll
            for (int dd = 1; dd < 11; dd++) m = fmaxf(m, sv[dd]);
            float ev[11], sum = 0.f;
#pragma unroll
            for (int dd = 0; dd < 11; dd++) { float e = expf(sv[dd] - m); ev[dd] = e; sum += e; }
            float inv = 1.f / sum;
#pragma unroll
            for (int i = 0; i < 64; i++) o[i] = 0.f;
#pragma unroll
            for (int dd = 0; dd < 11; dd++) {
                int j = row + deltas[dd];
                if ((unsigned)j < 128u) {
                    float wj = ev[dd] * inv;
                    const float* vp = &Vs[j * LDF + c0];
#pragma unroll
                    for (int i = 0; i < 16; i++) {
                        float4 vv = *(const float4*)&vp[i * 4];
                        o[4*i]   = fmaf(wj, vv.x, o[4*i]);
                        o[4*i+1] = fmaf(wj, vv.y, o[4*i+1]);
                        o[4*i+2] = fmaf(wj, vv.z, o[4*i+2]);
                        o[4*i+3] = fmaf(wj, vv.w, o[4*i+3]);
                    }
                }
            }
        }
        __syncthreads();                                     // all Q reads done
        stage_rowvals(o, smem, row, c0);                     // O -> H buffers
        __syncthreads();                                     // O staged

        gemm_mma(a_hi_lane, a_lo_lane, g_wfrag + (4*l + 3) * 4096 + wfoff, mw, d);
        __syncthreads();                                     // all O reads done
        if (l < 3) {
            epi_bf16(d, smem, bo + l * 128, mw, nw, lane);   // H_new staged
        } else {
            float* ob = out + (size_t)bi * 8388608 + (size_t)t * 128;
            epi_out(d, ob, bo + l * 128, mw, nw, lane);
        }
    }
}

extern "C" void kernel_launch(void* const* d_in, const int* in_sizes, int n_in,
                              void* d_out, int out_size)
{
    const float* x  = (const float*)d_in[0];
    const float* Wq = (const float*)d_in[1];
    const float* bq = (const float*)d_in[2];
    const float* Wk = (const float*)d_in[3];
    const float* bk = (const float*)d_in[4];
    const float* Wv = (const float*)d_in[5];
    const float* bv = (const float*)d_in[6];
    const float* Wo = (const float*)d_in[7];
    const float* bo = (const float*)d_in[8];
    float* out = (float*)d_out;

    const int NB = in_sizes[0] / (128 * TT * 128);   // batch (4)

    prep_w<<<17, 256>>>(Wq, Wk, Wv, Wo);

    cudaFuncSetAttribute(hattn_mma, cudaFuncAttributeMaxDynamicSharedMemorySize, SMEM_TOTAL);
    hattn_mma<<<NB * TT, NTHREADS, SMEM_TOTAL>>>(x, bq, bk, bv, bo, out);
}

// round 9
// speedup vs baseline: 1.1057x; 1.0725x over previous
#include <cuda_runtime.h>
#include <cuda_bf16.h>
#include <cstdint>

// HarmonicAwaredAttention via warp-level HMMA (mma.sync, arch-agnostic PTX).
// R9: 512 threads (16 warps -> 4/SMSP), warp grid 4(M)x4(N), tile 32x32.
// Same total MMA/LDSM/LDS work as R8, 2x the latency-hiding parallelism.
// K/V smem: LDF=144 + 4-float skew per 32-col group -> conflict-free LDS.128.
// GEMMs: m16n8k16 bf16 MMA, fp32 emulated with bf16 hi/lo 3-term split.

#define TT 512
#define NTHREADS 512
#define LDH_B  272            // bf16 row stride in bytes (136 elems)
#define LDKV   144            // fp32 row stride (floats) for K/V, skewed
#define LDQ    132            // fp32 row stride (floats) for Q overlay

// smem byte offsets
#define HHI_OFF 0
#define HLO_OFF 34816
#define QS_OFF  0              // fp32 Q overlays H region (sequenced by syncs)
#define KS_OFF  69632
#define VS_OFF  143360
#define SMEM_TOTAL 217088

// weights, fragment-linear uint4: [gemm][ks 0..7][j 0..15][lane 0..31]
// uint4 = {bh.x, bh.y, bl.x, bl.y}
__device__ __align__(16) uint4 g_wfrag[16 * 4096];
__device__ float g_pe[128 * 128];     // g_pe[c*128 + f]

__device__ __forceinline__ uint32_t smem_u32(const void* p) {
    uint32_t a;
    asm("{ .reg .u64 t; cvta.to.shared.u64 t, %1; cvt.u32.u64 %0, t; }" : "=r"(a) : "l"(p));
    return a;
}

#define LDSM(r, addr) \
    asm volatile("ldmatrix.sync.aligned.m8n8.x4.shared.b16 {%0,%1,%2,%3}, [%4];" \
        : "=r"((r)[0]), "=r"((r)[1]), "=r"((r)[2]), "=r"((r)[3]) : "r"(addr))

#define MMA(dp, a, bx, by) \
    asm volatile("mma.sync.aligned.m16n8k16.row.col.f32.bf16.bf16.f32 " \
        "{%0,%1,%2,%3},{%4,%5,%6,%7},{%8,%9},{%0,%1,%2,%3};" \
        : "+f"((dp)[0]), "+f"((dp)[1]), "+f"((dp)[2]), "+f"((dp)[3]) \
        : "r"((a)[0]), "r"((a)[1]), "r"((a)[2]), "r"((a)[3]), "r"(bx), "r"(by))

// ---------------- prologue: fragment-pack weights + PE table ----------------
// gemm g = 4*layer + {0:Wk,1:Wv,2:Wq,3:Wo}.  B[n][k] = W[k][n].
// entry e: lane=e&31, j=(e>>5)&15 (n-tile), ks=e>>9.
// lane fragment: n = 8j + (lane>>2); k0 = 16ks + 2(lane&3).
__global__ void prep_w(const float* __restrict__ Wq, const float* __restrict__ Wk,
                       const float* __restrict__ Wv, const float* __restrict__ Wo)
{
    int g = blockIdx.x;
    if (g == 16) {   // PE table
        for (int idx = threadIdx.x; idx < 128 * 128; idx += blockDim.x) {
            int c = idx >> 7, f = idx & 127;
            float e     = (float)(c & ~1) * (1.0f / 128.0f);
            float denom = exp2f(e * 13.287712379549449f);   // 10000^(i/128)
            float ang   = (float)f / denom;
            g_pe[c * 128 + f] = (c & 1) ? cosf(ang) : sinf(ang);
        }
        return;
    }
    int l = g >> 2, m = g & 3;
    const float* src = (m == 0 ? Wk : m == 1 ? Wv : m == 2 ? Wq : Wo) + l * 16384;
    for (int e = threadIdx.x; e < 4096; e += blockDim.x) {
        int lane = e & 31, j = (e >> 5) & 15, ks = e >> 9;
        int n  = 8 * j + (lane >> 2);
        int k0 = 16 * ks + 2 * (lane & 3);
        float w00 = src[k0 * 128 + n],       w01 = src[(k0 + 1) * 128 + n];
        float w10 = src[(k0 + 8) * 128 + n], w11 = src[(k0 + 9) * 128 + n];
        __nv_bfloat162 h0 = __floats2bfloat162_rn(w00, w01);
        __nv_bfloat162 h1 = __floats2bfloat162_rn(w10, w11);
        float2 f0 = __bfloat1622float2(h0), f1 = __bfloat1622float2(h1);
        __nv_bfloat162 l0 = __floats2bfloat162_rn(w00 - f0.x, w01 - f0.y);
        __nv_bfloat162 l1 = __floats2bfloat162_rn(w10 - f1.x, w11 - f1.y);
        uint4 o;
        o.x = *(uint32_t*)&h0;  o.y = *(uint32_t*)&h1;
        o.z = *(uint32_t*)&l0;  o.w = *(uint32_t*)&l1;
        g_wfrag[g * 4096 + e] = o;
    }
}

// ------------- GEMM: warp (mw,nw) computes D[32 rows x 32 cols] -------------
// d[mt*4 + jj][4]: mt in 0..1 (16-row tiles), jj in 0..3 (8-col tiles).
// wf pre-offset: g_wfrag + g*4096 + (4*nw)*32 + lane.
__device__ __forceinline__ void gemm_mma(uint32_t a_hi_lane, uint32_t a_lo_lane,
                                         const uint4* __restrict__ wf,
                                         int mw, float (*d)[4])
{
#pragma unroll
    for (int i = 0; i < 8; i++) { d[i][0] = 0.f; d[i][1] = 0.f; d[i][2] = 0.f; d[i][3] = 0.f; }

    uint4 b[4];
#pragma unroll
    for (int jj = 0; jj < 4; jj++) b[jj] = __ldg(wf + jj * 32);

    const uint32_t a_row_off = (uint32_t)(mw * 32) * LDH_B;

#pragma unroll
    for (int ks = 0; ks < 8; ks++) {
        uint32_t ah[2][4], al[2][4];
#pragma unroll
        for (int mt = 0; mt < 2; mt++) {
            uint32_t off = a_row_off + (uint32_t)(mt * 16) * LDH_B + (uint32_t)ks * 32;
            LDSM(ah[mt], a_hi_lane + off);
            LDSM(al[mt], a_lo_lane + off);
        }
        uint4 nb[4];
        {   // wrap-around prefetch (ks=7 reloads ks=0; harmless, unconditional)
            const uint4* p = wf + (((ks + 1) & 7) * 512);
#pragma unroll
            for (int jj = 0; jj < 4; jj++) nb[jj] = __ldg(p + jj * 32);
        }
#pragma unroll
        for (int mt = 0; mt < 2; mt++) {
#pragma unroll
            for (int jj = 0; jj < 4; jj++) {
                MMA(d[mt * 4 + jj], ah[mt], b[jj].x, b[jj].y);   // Ah*Bh
                MMA(d[mt * 4 + jj], ah[mt], b[jj].z, b[jj].w);   // Ah*Bl
                MMA(d[mt * 4 + jj], al[mt], b[jj].x, b[jj].y);   // Al*Bh
            }
        }
#pragma unroll
        for (int jj = 0; jj < 4; jj++) b[jj] = nb[jj];
    }
}

// D + bias -> fp32 smem buffer; stride ldf, column skew cs (floats).
__device__ __forceinline__ void epi_f32(float (*d)[4], float* buf, const float* bias,
                                        int mw, int nw, int lane, int ldf, int cs)
{
    int rq = lane >> 2, cq = 2 * (lane & 3);
#pragma unroll
    for (int jj = 0; jj < 4; jj++) {
        int c = 32 * nw + 8 * jj + cq;
        float b0 = __ldg(&bias[c]), b1 = __ldg(&bias[c + 1]);
#pragma unroll
        for (int mt = 0; mt < 2; mt++) {
            int r0 = 32 * mw + 16 * mt + rq;
            float2 v0 = make_float2(d[mt*4+jj][0] + b0, d[mt*4+jj][1] + b1);
            float2 v1 = make_float2(d[mt*4+jj][2] + b0, d[mt*4+jj][3] + b1);
            *(float2*)&buf[r0 * ldf + c + cs]       = v0;
            *(float2*)&buf[(r0 + 8) * ldf + c + cs] = v1;
        }
    }
}

// D + bias -> bf16 hi/lo H buffers
__device__ __forceinline__ void epi_bf16(float (*d)[4], unsigned char* sm,
                                         const float* bias, int mw, int nw, int lane)
{
    int rq = lane >> 2, cq = 2 * (lane & 3);
#pragma unroll
    for (int jj = 0; jj < 4; jj++) {
        int c = 32 * nw + 8 * jj + cq;
        float b0 = __ldg(&bias[c]), b1 = __ldg(&bias[c + 1]);
#pragma unroll
        for (int mt = 0; mt < 2; mt++) {
            int r0 = 32 * mw + 16 * mt + rq;
#pragma unroll
            for (int hh = 0; hh < 2; hh++) {
                int r = r0 + 8 * hh;
                float v0 = d[mt*4+jj][2*hh]     + b0;
                float v1 = d[mt*4+jj][2*hh + 1] + b1;
                __nv_bfloat162 hi2 = __floats2bfloat162_rn(v0, v1);
                float2 hf = __bfloat1622float2(hi2);
                __nv_bfloat162 lo2 = __floats2bfloat162_rn(v0 - hf.x, v1 - hf.y);
                *(uint32_t*)(sm + HHI_OFF + r * LDH_B + c * 2) = *(uint32_t*)&hi2;
                *(uint32_t*)(sm + HLO_OFF + r * LDH_B + c * 2) = *(uint32_t*)&lo2;
            }
        }
    }
}

// D + bias -> gmem out (transposed: out[c][r], channel stride 65536)
__device__ __forceinline__ void epi_out(float (*d)[4], float* ob, const float* bias,
                                        int mw, int nw, int lane)
{
    int rq = lane >> 2, cq = 2 * (lane & 3);
#pragma unroll
    for (int jj = 0; jj < 4; jj++) {
        int c = 32 * nw + 8 * jj + cq;
        float b0 = __ldg(&bias[c]), b1 = __ldg(&bias[c + 1]);
#pragma unroll
        for (int mt = 0; mt < 2; mt++) {
            int r0 = 32 * mw + 16 * mt + rq;
            ob[(size_t)c * 65536 + r0]           = d[mt*4+jj][0] + b0;
            ob[(size_t)(c + 1) * 65536 + r0]     = d[mt*4+jj][1] + b1;
            ob[(size_t)c * 65536 + r0 + 8]       = d[mt*4+jj][2] + b0;
            ob[(size_t)(c + 1) * 65536 + r0 + 8] = d[mt*4+jj][3] + b1;
        }
    }
}

// 32 fp32 vals (one row, one 32-col group) -> bf16 hi/lo into H buffers
__device__ __forceinline__ void stage_rowvals(const float* v, unsigned char* sm,
                                              int row, int c0)
{
#pragma unroll
    for (int i = 0; i < 16; i++) {
        float a = v[2 * i], b = v[2 * i + 1];
        __nv_bfloat162 hi2 = __floats2bfloat162_rn(a, b);
        float2 hf = __bfloat1622float2(hi2);
        __nv_bfloat162 lo2 = __floats2bfloat162_rn(a - hf.x, b - hf.y);
        *(uint32_t*)(sm + HHI_OFF + row * LDH_B + (c0 + 2 * i) * 2) = *(uint32_t*)&hi2;
        *(uint32_t*)(sm + HLO_OFF + row * LDH_B + (c0 + 2 * i) * 2) = *(uint32_t*)&lo2;
    }
}

extern __shared__ unsigned char smem[];

__global__ void __launch_bounds__(NTHREADS, 1)
hattn_mma(const float* __restrict__ x,
          const float* __restrict__ bq, const float* __restrict__ bk,
          const float* __restrict__ bv, const float* __restrict__ bo,
          float* __restrict__ out)
{
    const int tid = threadIdx.x;
    const int w = tid >> 5, lane = tid & 31;
    const int mw = w & 3, nw = w >> 2;          // warp grid 4(M) x 4(N)
    const int bi = blockIdx.x / TT;
    const int t  = blockIdx.x % TT;

    float* Qs = (float*)(smem + QS_OFF);
    float* Ks = (float*)(smem + KS_OFF);
    float* Vs = (float*)(smem + VS_OFF);

    const uint32_t smbase = smem_u32(smem);
    const uint32_t a_hi_lane = smbase + HHI_OFF + (lane & 15) * LDH_B + (lane >> 4) * 16;
    const uint32_t a_lo_lane = smbase + HLO_OFF + (lane & 15) * LDH_B + (lane >> 4) * 16;

    const int wfoff = (4 * nw) * 32 + lane;     // B fragment base offset for this warp

    // attention / staging mapping: thread owns (row, 32-col group qg)
    const int row = tid >> 2;
    const int qg  = tid & 3;                    // head = qg>>1, half = qg&1
    const int c0  = 32 * qg;
    const int kvs = c0 + 4 * qg;                // skewed col offset into Ks/Vs

    // ---- stage H = x + PE ----
    {
        const float* xb = x + (size_t)bi * 8388608 + (size_t)t * 128;
        float v[32];
#pragma unroll
        for (int c = 0; c < 32; c++)
            v[c] = xb[(size_t)(c0 + c) * 65536 + row] + g_pe[(c0 + c) * 128 + row];
        stage_rowvals(v, smem, row, c0);
    }

    const int deltas[11] = {-124, -111, -96, -76, -48, 0, 48, 76, 96, 111, 124};
    float d[8][4];

#pragma unroll 1
    for (int l = 0; l < 4; l++) {
        __syncthreads();                                     // H staged/visible

        gemm_mma(a_hi_lane, a_lo_lane, g_wfrag + (4*l + 0) * 4096 + wfoff, mw, d);
        epi_f32(d, Ks, bk + l * 128, mw, nw, lane, LDKV, 4 * nw);
        gemm_mma(a_hi_lane, a_lo_lane, g_wfrag + (4*l + 1) * 4096 + wfoff, mw, d);
        epi_f32(d, Vs, bv + l * 128, mw, nw, lane, LDKV, 4 * nw);
        gemm_mma(a_hi_lane, a_lo_lane, g_wfrag + (4*l + 2) * 4096 + wfoff, mw, d);
        __syncthreads();                                     // all H reads done
        epi_f32(d, Qs, bq + l * 128, mw, nw, lane, LDQ, 0);  // Q overlays H region
        __syncthreads();                                     // Q/K/V visible

        // ---- sparse harmonic attention: thread owns (row, qg) ----
        float o[32];
        {
            float q[32];
            const float* qp = &Qs[row * LDQ + c0];
#pragma unroll
            for (int i = 0; i < 32; i++) q[i] = qp[i];

            float sv[11];
#pragma unroll
            for (int dd = 0; dd < 11; dd++) {
                int j = row + deltas[dd];
                float s = -1e30f;
                if ((unsigned)j < 128u) {
                    const float* kp = &Ks[j * LDKV + kvs];
                    float a = 0.f;
#pragma unroll
                    for (int i = 0; i < 8; i++) {
                        float4 kk = *(const float4*)&kp[i * 4];
                        a = fmaf(q[4*i],   kk.x, a);
                        a = fmaf(q[4*i+1], kk.y, a);
                        a = fmaf(q[4*i+2], kk.z, a);
                        a = fmaf(q[4*i+3], kk.w, a);
                    }
                    // combine the two 32-col halves of this head (lane partner lane^1)
                    a += __shfl_xor_sync(0xffffffffu, a, 1);
                    s = a * 0.125f;    // 1/sqrt(64)
                } else {
                    // keep shuffle uniform across the pair (both sides take same path)
                    float dummy = 0.f;
                    dummy += __shfl_xor_sync(0xffffffffu, dummy, 1);
                }
                sv[dd] = s;
            }
            float m = sv[0];
#pragma unroll
            for (int dd = 1; dd < 11; dd++) m = fmaxf(m, sv[dd]);
            float ev[11], sum = 0.f;
#pragma unroll
            for (int dd = 0; dd < 11; dd++) { float e = __expf(sv[dd] - m); ev[dd] = e; sum += e; }
            float inv = __fdividef(1.f, sum);
#pragma unroll
            for (int i = 0; i < 32; i++) o[i] = 0.f;
#pragma unroll
            for (int dd = 0; dd < 11; dd++) {
                int j = row + deltas[dd];
                if ((unsigned)j < 128u) {
                    float wj = ev[dd] * inv;
                    const float* vp = &Vs[j * LDKV + kvs];
#pragma unroll
                    for (int i = 0; i < 8; i++) {
                        float4 vv = *(const float4*)&vp[i * 4];
                        o[4*i]   = fmaf(wj, vv.x, o[4*i]);
                        o[4*i+1] = fmaf(wj, vv.y, o[4*i+1]);
                        o[4*i+2] = fmaf(wj, vv.z, o[4*i+2]);
                        o[4*i+3] = fmaf(wj, vv.w, o[4*i+3]);
                    }
                }
            }
        }
        __syncthreads();                                     // all Q reads done
        stage_rowvals(o, smem, row, c0);                     // O -> H buffers
        __syncthreads();                                     // O staged

        gemm_mma(a_hi_lane, a_lo_lane, g_wfrag + (4*l + 3) * 4096 + wfoff, mw, d);
        __syncthreads();                                     // all O reads done
        if (l < 3) {
            epi_bf16(d, smem, bo + l * 128, mw, nw, lane);   // H_new staged
        } else {
            float* ob = out + (size_t)bi * 8388608 + (size_t)t * 128;
            epi_out(d, ob, bo + l * 128, mw, nw, lane);
        }
    }
}

extern "C" void kernel_launch(void* const* d_in, const int* in_sizes, int n_in,
                              void* d_out, int out_size)
{
    const float* x  = (const float*)d_in[0];
    const float* Wq = (const float*)d_in[1];
    const float* bq = (const float*)d_in[2];
    const float* Wk = (const float*)d_in[3];
    const float* bk = (const float*)d_in[4];
    const float* Wv = (const float*)d_in[5];
    const float* bv = (const float*)d_in[6];
    const float* Wo = (const float*)d_in[7];
    const float* bo = (const float*)d_in[8];
    float* out = (float*)d_out;

    const int NB = in_sizes[0] / (128 * TT * 128);   // batch (4)

    prep_w<<<17, 256>>>(Wq, Wk, Wv, Wo);

    cudaFuncSetAttribute(hattn_mma, cudaFuncAttributeMaxDynamicSharedMemorySize, SMEM_TOTAL);
    hattn_mma<<<NB * TT, NTHREADS, SMEM_TOTAL>>>(x, bq, bk, bv, bo, out);
}